// round 5
// baseline (speedup 1.0000x reference)
#include <cuda_runtime.h>
#include <cuda_bf16.h>
#include <cstdint>

// ============================================================================
// HiPPO-LegT scan via chunked GEMM on mma.sync (HMMA, works on base sm_103).
//   c_t = A c_{t-1} + f_t B ;  out (512, 2048, 64)
// Chunk T=16:  c_{t0+j} = A^{j+1} c_in + sum_{i<=j} (A^{j-i} B) f_{t0+i}
//   => OUT(perm)[c][(j,n)] = sum_k X[c][k] * G[(j,n)][k],  K = 64 + 16 = 80
// where X[c] = [c_in ; f_chunk] for column c = chunk*2048 + seq.
// bf16 hi/lo split, 3 MMA passes (hh, lh, hl) => ~2^-18 relative accuracy.
// Pipeline: 4x A-power doubling kernels -> G build -> boundary scan -> GEMM.
// ============================================================================

static constexpr int TCH    = 16;
static constexpr int NCHUNK = 32;
static constexpr int NSEQ   = 2048;
static constexpr int NCOLS  = NSEQ * NCHUNK;   // 65536
static constexpr int KREAL  = 80;
static constexpr int SEQLEN = 512;
static constexpr int KPAD   = 88;              // bf16 elems per smem row (conflict-free)
static constexpr int KPADW  = 44;              // 32-bit words per smem row

// ---- device scratch (static; no cudaMalloc) ----
__device__ __align__(16) float          g_Apow[17][4096];
__device__ __align__(16) float          g_Kvec[16 * 64];
__device__ __align__(16) __nv_bfloat16  g_Ghi[1024 * KREAL];
__device__ __align__(16) __nv_bfloat16  g_Glo[1024 * KREAL];
__device__ __align__(16) __nv_bfloat16  g_Xhi[(size_t)NCOLS * KREAL];
__device__ __align__(16) __nv_bfloat16  g_Xlo[(size_t)NCOLS * KREAL];

// ---- packed f32x2 helpers ----
__device__ __forceinline__ double fma2(double a, double b, double c) {
    double d;
    asm("fma.rn.f32x2 %0, %1, %2, %3;" : "=d"(d) : "d"(a), "d"(b), "d"(c));
    return d;
}
__device__ __forceinline__ double add2(double a, double b) {
    double d;
    asm("add.rn.f32x2 %0, %1, %2;" : "=d"(d) : "d"(a), "d"(b));
    return d;
}
__device__ __forceinline__ double pack2(float lo, float hi) {
    double d;
    asm("mov.b64 %0, {%1, %2};" : "=d"(d) : "f"(lo), "f"(hi));
    return d;
}
__device__ __forceinline__ void unpack2(double d, float& lo, float& hi) {
    asm("mov.b64 {%0, %1}, %2;" : "=f"(lo), "=f"(hi) : "d"(d));
}

// ---- bf16 mma.sync m16n8k16 (row.col, f32 accum) ----
__device__ __forceinline__ void mma16816(float* d, const uint32_t* a, const uint32_t* b) {
    asm volatile(
        "mma.sync.aligned.m16n8k16.row.col.f32.bf16.bf16.f32 "
        "{%0,%1,%2,%3}, {%4,%5,%6,%7}, {%8,%9}, {%0,%1,%2,%3};\n"
        : "+f"(d[0]), "+f"(d[1]), "+f"(d[2]), "+f"(d[3])
        : "r"(a[0]), "r"(a[1]), "r"(a[2]), "r"(a[3]), "r"(b[0]), "r"(b[1]));
}

// ============================================================================
// A-power doubling level:  A^(Bv+q) = A^Bv * A^q  for q = 1..Bv.
// grid = Bv*16 CTAs, 256 threads; each CTA computes 256 output elements.
// ============================================================================
__global__ __launch_bounds__(256) void pow_level_kernel(const float* __restrict__ A, int Bv) {
    __shared__ __align__(16) float sL[4096];
    __shared__ __align__(16) float sR[4096];
    const int q   = (blockIdx.x >> 4) + 1;
    const int dst = Bv + q;
    const float* Lp = (Bv == 1) ? A : g_Apow[Bv];
    const float* Rp = (q  == 1) ? A : g_Apow[q];
    const int tid = threadIdx.x;
    for (int i = tid; i < 4096; i += 256) { sL[i] = Lp[i]; sR[i] = Rp[i]; }
    __syncthreads();

    const int e   = (blockIdx.x & 15) * 256 + tid;
    const int row = e >> 6, col = e & 63;
    float a0 = 0.f, a1 = 0.f, a2 = 0.f, a3 = 0.f;
    #pragma unroll
    for (int m = 0; m < 64; m += 4) {
        a0 = fmaf(sL[row * 64 + m],     sR[(m)     * 64 + col], a0);
        a1 = fmaf(sL[row * 64 + m + 1], sR[(m + 1) * 64 + col], a1);
        a2 = fmaf(sL[row * 64 + m + 2], sR[(m + 2) * 64 + col], a2);
        a3 = fmaf(sL[row * 64 + m + 3], sR[(m + 3) * 64 + col], a3);
    }
    g_Apow[dst][e] = (a0 + a1) + (a2 + a3);
    if (Bv == 1) g_Apow[1][e] = A[e];      // stash A itself once
}

// ============================================================================
// G build (+ Kvec for the boundary scan).  17 CTAs x 64 threads.
//   CTA j<16: thread n writes G row r=j*64+n (bf16 hi/lo).
//   CTA 16:   thread n writes g_Kvec[d*64+n] = (A^d B)[n].
// ============================================================================
__global__ __launch_bounds__(64) void gbuild_kernel(const float* __restrict__ Bvec) {
    __shared__ __align__(16) float sB[64];
    const int j = blockIdx.x, n = threadIdx.x;
    sB[n] = Bvec[n];
    __syncthreads();

    auto dotAB = [&](int d) -> float {
        const float4* ap = reinterpret_cast<const float4*>(&g_Apow[d][n * 64]);
        const float4* bp = reinterpret_cast<const float4*>(sB);
        float s0 = 0.f, s1 = 0.f, s2 = 0.f, s3 = 0.f;
        #pragma unroll
        for (int v = 0; v < 16; v++) {
            float4 a = ap[v], b = bp[v];
            s0 = fmaf(a.x, b.x, s0); s1 = fmaf(a.y, b.y, s1);
            s2 = fmaf(a.z, b.z, s2); s3 = fmaf(a.w, b.w, s3);
        }
        return (s0 + s1) + (s2 + s3);
    };

    if (j < 16) {
        const int r = j * 64 + n;
        for (int k = 0; k < 64; k++) {
            float v = g_Apow[j + 1][n * 64 + k];
            __nv_bfloat16 h = __float2bfloat16(v);
            g_Ghi[r * KREAL + k] = h;
            g_Glo[r * KREAL + k] = __float2bfloat16(v - __bfloat162float(h));
        }
        for (int i = 0; i < 16; i++) {
            const int d = j - i;
            float v = (d < 0) ? 0.0f : ((d == 0) ? sB[n] : dotAB(d));
            __nv_bfloat16 h = __float2bfloat16(v);
            g_Ghi[r * KREAL + 64 + i] = h;
            g_Glo[r * KREAL + 64 + i] = __float2bfloat16(v - __bfloat162float(h));
        }
    } else {
        for (int d = 0; d < 16; d++)
            g_Kvec[d * 64 + n] = (d == 0) ? sB[n] : dotAB(d);
    }
}

// ============================================================================
// Boundary scan (fp32, f32x2-packed) + X build (bf16 hi/lo).
// 2048 CTAs x 64 threads; thread n owns state row n; one barrier per chunk.
// ============================================================================
__global__ __launch_bounds__(64) void phase1_kernel(const float* __restrict__ xin) {
    const int seq = blockIdx.x, n = threadIdx.x;
    __shared__ __align__(16) float c_sm[2][64];
    __shared__ __align__(16) float f_sm[2][16];

    double a16[32];
    {
        const double* r = reinterpret_cast<const double*>(&g_Apow[16][n * 64]);
        #pragma unroll
        for (int i = 0; i < 32; i++) a16[i] = r[i];
    }
    double wp[8];   // w[i] = Kvec[15-i][n], packed over i pairs
    #pragma unroll
    for (int i = 0; i < 8; i++)
        wp[i] = pack2(g_Kvec[(15 - 2 * i) * 64 + n], g_Kvec[(14 - 2 * i) * 64 + n]);

    float cmy = 0.0f;
    c_sm[0][n] = 0.0f;

    for (int k = 0; k < NCHUNK; k++) {
        const int buf = k & 1;
        const size_t col = (size_t)k * NSEQ + seq;
        {   // X: state part (hi/lo split of incoming boundary state)
            __nv_bfloat16 h = __float2bfloat16(cmy);
            g_Xhi[col * KREAL + n] = h;
            g_Xlo[col * KREAL + n] = __float2bfloat16(cmy - __bfloat162float(h));
        }
        if (n < 16) {   // X: f part
            const float f = xin[(size_t)seq * SEQLEN + k * TCH + n];
            f_sm[buf][n] = f;
            __nv_bfloat16 h = __float2bfloat16(f);
            g_Xhi[col * KREAL + 64 + n] = h;
            g_Xlo[col * KREAL + 64 + n] = __float2bfloat16(f - __bfloat162float(h));
        }
        __syncthreads();   // publishes f_sm[buf] and c_sm[buf] (written last iter)

        const double2* cp = reinterpret_cast<const double2*>(c_sm[buf]);
        double acc0 = 0.0, acc1 = 0.0, acc2 = 0.0, acc3 = 0.0;
        #pragma unroll
        for (int i = 0; i < 8; i++) {
            const double2 ca = cp[2 * i], cb = cp[2 * i + 1];
            acc0 = fma2(a16[4 * i],     ca.x, acc0);
            acc1 = fma2(a16[4 * i + 1], ca.y, acc1);
            acc2 = fma2(a16[4 * i + 2], cb.x, acc2);
            acc3 = fma2(a16[4 * i + 3], cb.y, acc3);
        }
        const double* fp = reinterpret_cast<const double*>(f_sm[buf]);
        acc0 = fma2(wp[0], fp[0], acc0); acc1 = fma2(wp[1], fp[1], acc1);
        acc2 = fma2(wp[2], fp[2], acc2); acc3 = fma2(wp[3], fp[3], acc3);
        acc0 = fma2(wp[4], fp[4], acc0); acc1 = fma2(wp[5], fp[5], acc1);
        acc2 = fma2(wp[6], fp[6], acc2); acc3 = fma2(wp[7], fp[7], acc3);

        const double s = add2(add2(acc0, acc1), add2(acc2, acc3));
        float x, y;
        unpack2(s, x, y);
        cmy = x + y;
        c_sm[buf ^ 1][n] = cmy;
    }
}

// ============================================================================
// GEMM: D(64x64) = Xtile(64x80) . Gtile(64x80)^T  via mma.sync, 3 bf16 passes.
// grid (1024, 16), 128 threads.  Static smem 45 KB.  Warp tile 16 x 64.
// ============================================================================
__global__ __launch_bounds__(128) void gemm_kernel(float* __restrict__ out) {
    __shared__ __align__(16) __nv_bfloat16 sXh[64 * KPAD];
    __shared__ __align__(16) __nv_bfloat16 sXl[64 * KPAD];
    __shared__ __align__(16) __nv_bfloat16 sGh[64 * KPAD];
    __shared__ __align__(16) __nv_bfloat16 sGl[64 * KPAD];

    const int tid   = threadIdx.x;
    const int mbase = blockIdx.x * 64;   // global X-column base
    const int jt    = blockIdx.y;        // j (chunk-local time)

    // ---- tile loads: threads 0..63 -> X rows, 64..127 -> G rows ----
    if (tid < 64) {
        const uint4* hv = reinterpret_cast<const uint4*>(g_Xhi + (size_t)(mbase + tid) * KREAL);
        const uint4* lv = reinterpret_cast<const uint4*>(g_Xlo + (size_t)(mbase + tid) * KREAL);
        uint4* dh = reinterpret_cast<uint4*>(sXh + tid * KPAD);
        uint4* dl = reinterpret_cast<uint4*>(sXl + tid * KPAD);
        #pragma unroll
        for (int v = 0; v < 10; v++) { dh[v] = hv[v]; dl[v] = lv[v]; }
    } else {
        const int r = tid - 64;
        const uint4* hv = reinterpret_cast<const uint4*>(g_Ghi + (size_t)(jt * 64 + r) * KREAL);
        const uint4* lv = reinterpret_cast<const uint4*>(g_Glo + (size_t)(jt * 64 + r) * KREAL);
        uint4* dh = reinterpret_cast<uint4*>(sGh + r * KPAD);
        uint4* dl = reinterpret_cast<uint4*>(sGl + r * KPAD);
        #pragma unroll
        for (int v = 0; v < 10; v++) { dh[v] = hv[v]; dl[v] = lv[v]; }
    }
    __syncthreads();

    const int w   = tid >> 5;
    const int l   = tid & 31;
    const int gr  = l >> 2;      // 0..7
    const int gkw = l & 3;       // word within k16
    const uint32_t* XhW = reinterpret_cast<const uint32_t*>(sXh);
    const uint32_t* XlW = reinterpret_cast<const uint32_t*>(sXl);
    const uint32_t* GhW = reinterpret_cast<const uint32_t*>(sGh);
    const uint32_t* GlW = reinterpret_cast<const uint32_t*>(sGl);

    float acc[8][4];
    #pragma unroll
    for (int nt = 0; nt < 8; nt++)
        #pragma unroll
        for (int i = 0; i < 4; i++) acc[nt][i] = 0.0f;

    #pragma unroll
    for (int ks = 0; ks < 5; ks++) {          // K = 5 * 16 = 80 exactly
        const int kw = ks * 8 + gkw;
        const int r0 = (16 * w + gr) * KPADW + kw;
        const int r1 = r0 + 8 * KPADW;
        uint32_t ah[4] = { XhW[r0], XhW[r1], XhW[r0 + 4], XhW[r1 + 4] };
        uint32_t al[4] = { XlW[r0], XlW[r1], XlW[r0 + 4], XlW[r1 + 4] };
        #pragma unroll
        for (int nt = 0; nt < 8; nt++) {
            const int b0 = (nt * 8 + gr) * KPADW + kw;
            uint32_t bh[2] = { GhW[b0], GhW[b0 + 4] };
            uint32_t bl[2] = { GlW[b0], GlW[b0 + 4] };
            mma16816(acc[nt], ah, bh);   // hi * hi
            mma16816(acc[nt], al, bh);   // lo * hi
            mma16816(acc[nt], ah, bl);   // hi * lo
        }
    }

    // ---- epilogue: row m -> (chunk, seq); 64 contiguous floats per row ----
    const int chunk = mbase >> 11;
    const int seqb  = mbase & 2047;
    const int gk    = (l & 3) * 2;
    #pragma unroll
    for (int s = 0; s < 2; s++) {
        const int m = 16 * w + gr + 8 * s;
        float* ob = out + ((size_t)(chunk * TCH + jt) * NSEQ + (seqb + m)) * 64 + gk;
        #pragma unroll
        for (int nt = 0; nt < 8; nt++) {
            float2 v = make_float2(acc[nt][2 * s], acc[nt][2 * s + 1]);
            *reinterpret_cast<float2*>(ob + nt * 8) = v;
        }
    }
}

// ============================================================================
extern "C" void kernel_launch(void* const* d_in, const int* in_sizes, int n_in,
                              void* d_out, int out_size) {
    const float* xin  = (const float*)d_in[0];  // (16,128,512)
    const float* Amat = (const float*)d_in[1];  // (64,64)
    const float* Bvec = (const float*)d_in[2];  // (64,)
    float* out = (float*)d_out;                 // (512,16,128,64)

    pow_level_kernel<<<16,  256>>>(Amat, 1);   // A^2   (+ store A^1)
    pow_level_kernel<<<32,  256>>>(Amat, 2);   // A^3..A^4
    pow_level_kernel<<<64,  256>>>(Amat, 4);   // A^5..A^8
    pow_level_kernel<<<128, 256>>>(Amat, 8);   // A^9..A^16
    gbuild_kernel<<<17, 64>>>(Bvec);
    phase1_kernel<<<NSEQ, 64>>>(xin);

    dim3 grid(NCOLS / 64, TCH);                // (1024, 16)
    gemm_kernel<<<grid, 128>>>(out);
}